// round 6
// baseline (speedup 1.0000x reference)
#include <cuda_runtime.h>
#include <cstdint>

#define M 8192
#define NW 128          // 64-bit words per row (M/64)
#define NMS_T 0.3f
#define CH 512          // scan chunk size (elements)
#define WPC 8           // words per chunk (CH/64)

typedef unsigned long long u64;

// ---------------- device scratch (no runtime allocation allowed) ------------
__device__ float g_d[M * 5];        // transformed detections (orig order)
__device__ u64   g_ckey[M];         // packed (key<<13 | idx) for valid entries
__device__ int   g_cnt;             // valid count (atomic; reset by scan)
__device__ int   g_V;               // valid count (published by sort)
__device__ float g_ds[M * 5];       // sorted detections (first V rows)
__device__ float4 g_boxes[M];       // x1,y1,x2,y2 (sorted order, first V)
__device__ float g_area[M];
__device__ u64   g_mask[M * NW];    // suppression bitmask (i>j bits only)

// ---------------- kernel 1: transform + score + compact valid ---------------
__global__ void prep_kernel(const float* __restrict__ det,
                            const float* __restrict__ off,
                            const float* __restrict__ scl,
                            const float* __restrict__ bnd) {
    int i = blockIdx.x * blockDim.x + threadIdx.x;
    if (i >= M) return;
    int w = i >> 10;
    const float* dp = det + i * 5;
    float d0 = off[w * 5 + 0] + dp[0] * scl[w * 5 + 0];
    float d1 = off[w * 5 + 1] + dp[1] * scl[w * 5 + 1];
    float d2 = off[w * 5 + 2] + dp[2] * scl[w * 5 + 2];
    float d3 = off[w * 5 + 3] + dp[3] * scl[w * 5 + 3];
    float d4 = off[w * 5 + 4] + dp[4] * scl[w * 5 + 4];
    float cx = dp[1], cy = dp[2];
    bool valid = (cx < bnd[w * 4 + 1]) && (cx > bnd[w * 4 + 0]) &&
                 (cy < bnd[w * 4 + 3]) && (cy > bnd[w * 4 + 2]);

    g_d[i * 5 + 0] = d0;
    g_d[i * 5 + 1] = d1;
    g_d[i * 5 + 2] = d2;
    g_d[i * 5 + 3] = d3;
    g_d[i * 5 + 4] = d4;

    // only entries with score>0 can be kept; others produce zero output rows
    if (valid && d0 > 0.0f) {
        unsigned key = ~(__float_as_uint(d0) | 0x80000000u);
        int pos = atomicAdd(&g_cnt, 1);
        g_ckey[pos] = ((u64)key << 13) | (u64)i;   // (score desc, idx asc)
    }
}

// ---------------- kernel 2: hybrid shuffle/smem bitonic sort + gather -------
extern "C" __global__ void __launch_bounds__(1024)
sort_kernel() {
    extern __shared__ u64 sv[];       // up to 8192 * 8B = 64KB dynamic
    int tid = threadIdx.x;
    int V = g_cnt;
    if (tid == 0) g_V = V;

    int P = 1024;
    while (P < V) P <<= 1;            // P in {1024..8192}
    int slots = P >> 10;

    for (int t = tid; t < P; t += 1024)
        sv[t] = (t < V) ? g_ckey[t] : ~0ull;
    __syncthreads();

    u64 r[8];

    // phase 1: k = 2..32 entirely in registers (all strides intra-warp)
#pragma unroll 4
    for (int i = 0; i < slots; i++) r[i] = sv[i * 1024 + tid];
    for (int k = 2; k <= 32; k <<= 1) {
        for (int s = k >> 1; s >= 1; s >>= 1) {
            for (int i = 0; i < slots; i++) {
                unsigned e = i * 1024 + tid;
                u64 o = __shfl_xor_sync(0xffffffffu, r[i], s);
                bool takeMin = (((e & s) == 0) == ((e & k) == 0));
                bool lt = r[i] < o;
                r[i] = (takeMin == lt) ? r[i] : o;
            }
        }
    }
#pragma unroll 4
    for (int i = 0; i < slots; i++) sv[i * 1024 + tid] = r[i];
    __syncthreads();

    // phase 2: k = 64..P, strides >=32 in smem, strides <=16 in registers
    for (int k = 64; k <= P; k <<= 1) {
        for (int s = k >> 1; s >= 32; s >>= 1) {
            for (int v = tid; v < (P >> 1); v += 1024) {
                int i = ((v & ~(s - 1)) << 1) | (v & (s - 1));
                int j = i + s;
                bool up = ((i & k) == 0);
                u64 a = sv[i], b = sv[j];
                if ((a > b) == up) { sv[i] = b; sv[j] = a; }
            }
            __syncthreads();
        }
#pragma unroll 4
        for (int i = 0; i < slots; i++) r[i] = sv[i * 1024 + tid];
        for (int s = 16; s >= 1; s >>= 1) {
            for (int i = 0; i < slots; i++) {
                unsigned e = i * 1024 + tid;
                u64 o = __shfl_xor_sync(0xffffffffu, r[i], s);
                bool takeMin = (((e & s) == 0) == ((e & k) == 0));
                bool lt = r[i] < o;
                r[i] = (takeMin == lt) ? r[i] : o;
            }
        }
#pragma unroll 4
        for (int i = 0; i < slots; i++) sv[i * 1024 + tid] = r[i];
        __syncthreads();
    }

    // gather sorted rows, build boxes/areas
    for (int j = tid; j < V; j += 1024) {
        int idx = (int)(sv[j] & 0x1FFFu);
        float dd[5];
#pragma unroll
        for (int c = 0; c < 5; c++) {
            dd[c] = g_d[idx * 5 + c];
            g_ds[j * 5 + c] = dd[c];
        }
        float x1 = dd[1] - 0.5f * dd[3];
        float y1 = dd[2] - 0.5f * dd[4];
        float x2 = dd[1] + 0.5f * dd[3];
        float y2 = dd[2] + 0.5f * dd[4];
        g_boxes[j] = make_float4(x1, y1, x2, y2);
        g_area[j] = fmaxf(x2 - x1, 0.0f) * fmaxf(y2 - y1, 0.0f);
    }
}

// ---------------- kernel 3: IoU suppression bitmask -------------------------
__global__ void mask_kernel() {
    int bx = blockIdx.x, by = blockIdx.y;
    if (bx < by) return;                       // only i > j bits needed
    int V = g_V;
    if ((by << 6) >= V || (bx << 6) >= V) return;

    __shared__ float4 cbox[64];
    __shared__ float  carea[64];
    int t = threadIdx.x;
    int ci = (bx << 6) + t;
    if (ci < V) {
        cbox[t] = g_boxes[ci];
        carea[t] = g_area[ci];
    } else {
        cbox[t] = make_float4(0.f, 0.f, 0.f, 0.f);
        carea[t] = 0.f;
    }
    __syncthreads();

    int j = (by << 6) + t;
    if (j >= V) return;
    float4 rb = g_boxes[j];
    float  ra = g_area[j];

    u64 bits = 0ull;
#pragma unroll
    for (int b = 0; b < 64; b++) {
        int i = (bx << 6) + b;
        if (i > j) {
            float iw = fminf(rb.z, cbox[b].z) - fmaxf(rb.x, cbox[b].x);
            float ih = fminf(rb.w, cbox[b].w) - fmaxf(rb.y, cbox[b].y);
            iw = fmaxf(iw, 0.0f);
            ih = fmaxf(ih, 0.0f);
            float inter = iw * ih;
            float uni = ra + carea[b] - inter;
            if (inter > NMS_T * fmaxf(uni, 1e-9f)) bits |= (1ull << b);
        }
    }
    g_mask[(size_t)j * NW + bx] = bits;
}

// ---------------- kernel 4: exact greedy NMS scan (512-wide) + output -------
__global__ void __launch_bounds__(1024) scan_kernel(float* __restrict__ out) {
    __shared__ u64 remv[NW];              // 1KB
    __shared__ u64 skeep[NW];             // 1KB
    __shared__ u64 sdiag[CH][WPC];        // 32KB diagonal block
    __shared__ u64 part[1024];            // 8KB propagation partials
    __shared__ unsigned short klist[CH];  // 1KB
    __shared__ int knum;
    int t = threadIdx.x;
    int V = g_V;
    int NC = (V + CH - 1) / CH;           // 512-wide chunks
    int NWv = (V + 63) >> 6;              // words containing valid entries

    if (t == 1023) g_cnt = 0;             // deterministic reset for next run
    if (t < NW) { remv[t] = 0ull; skeep[t] = 0ull; }
    part[t] = 0ull;

    // prefetch diag block of chunk 0 (row = i>>3, word = i&7)
    u64 d[4];
#pragma unroll
    for (int j = 0; j < 4; j++) {
        int i = t + j * 1024;
        d[j] = (NC > 0) ? g_mask[(size_t)(i >> 3) * NW + (i & 7)] : 0ull;
    }
    __syncthreads();

    int cprev = -1;
    for (int c = 0; c < NC; c++) {
        // store prefetched diag block
#pragma unroll
        for (int j = 0; j < 4; j++) {
            int i = t + j * 1024;
            sdiag[i >> 3][i & 7] = d[j];
        }
        // fold previous chunk's propagation partials (8 parts per word)
        if (cprev >= 0 && t < 120) {
            int w = cprev * WPC + WPC + t;
            if (w < NW) {
                u64 acc = 0ull;
#pragma unroll
                for (int s = 0; s < 8; s++) acc |= part[t * 8 + s];
                remv[w] |= acc;
            }
        }
        __syncthreads();

        // prefetch next chunk's diag block (latency hidden by greedy+prop)
        if (c + 1 < NC) {
#pragma unroll
            for (int j = 0; j < 4; j++) {
                int i = t + j * 1024;
                d[j] = g_mask[(size_t)((c + 1) * CH + (i >> 3)) * NW +
                              ((c + 1) * WPC + (i & 7))];
            }
        }

        if (t == 0) {
            u64 alive[WPC], kept[WPC];
            int base = c * WPC;
#pragma unroll
            for (int w = 0; w < WPC; w++) {
                int r = V - ((base + w) << 6);
                u64 vm = (r >= 64) ? ~0ull : (r <= 0 ? 0ull : ((1ull << r) - 1ull));
                alive[w] = ~remv[base + w] & vm;
                kept[w] = 0ull;
            }
            int n = 0;
            for (int w = 0; w < WPC; w++) {
                while (alive[w]) {
                    int b = __ffsll((long long)alive[w]) - 1;
                    int rr = (w << 6) + b;
                    kept[w] |= 1ull << b;
                    klist[n++] = (unsigned short)rr;
                    alive[w] &= ~(1ull << b);
                    for (int u = w; u < WPC; u++)
                        alive[u] &= ~sdiag[rr][u];
                }
            }
#pragma unroll
            for (int w = 0; w < WPC; w++) skeep[base + w] = kept[w];
            knum = n;
        }
        __syncthreads();

        // propagation: 8 threads per word, 4 accumulators (MLP 32/word)
        int w = c * WPC + WPC + (t >> 3);
        int sub = t & 7;
        u64 a0 = 0ull, a1 = 0ull, a2 = 0ull, a3 = 0ull;
        if (w < NWv) {
            const u64* bp = g_mask + (size_t)(c * CH) * NW + w;
            int n = knum;
            int i = sub;
            for (; i + 24 < n; i += 32) {
                a0 |= bp[(size_t)klist[i] * NW];
                a1 |= bp[(size_t)klist[i + 8] * NW];
                a2 |= bp[(size_t)klist[i + 16] * NW];
                a3 |= bp[(size_t)klist[i + 24] * NW];
            }
            for (; i < n; i += 8) a0 |= bp[(size_t)klist[i] * NW];
        }
        part[t] = (a0 | a1) | (a2 | a3);
        cprev = c;
        __syncthreads();
    }

    // fused masked output
    for (int j = t; j < M; j += 1024) {
        if (j < V) {
            u64 kw = skeep[j >> 6];
            float f = ((kw >> (j & 63)) & 1ull) ? 1.0f : 0.0f;
#pragma unroll
            for (int c = 0; c < 5; c++)
                out[j * 5 + c] = g_ds[j * 5 + c] * f;
        } else {
#pragma unroll
            for (int c = 0; c < 5; c++)
                out[j * 5 + c] = 0.0f;
        }
    }
}

// ---------------- launcher ---------------------------------------------------
extern "C" void kernel_launch(void* const* d_in, const int* in_sizes, int n_in,
                              void* d_out, int out_size) {
    const float* det = (const float*)d_in[0];
    const float* off = (const float*)d_in[1];
    const float* scl = (const float*)d_in[2];
    const float* bnd = (const float*)d_in[3];
    float* out = (float*)d_out;

    cudaFuncSetAttribute((const void*)sort_kernel,
                         cudaFuncAttributeMaxDynamicSharedMemorySize, 65536);

    prep_kernel<<<M / 256, 256>>>(det, off, scl, bnd);
    sort_kernel<<<1, 1024, 65536>>>();
    mask_kernel<<<dim3(NW, NW), 64>>>();
    scan_kernel<<<1, 1024>>>(out);
}